// round 9
// baseline (speedup 1.0000x reference)
#include <cuda_runtime.h>
#include <math.h>

#define N_NODES 100000
#define N_EDGES 3200000
#define F_IN    256
#define U       32
#define C       40

#define SCAN_CH   512
#define SCAN_NB   ((N_NODES + SCAN_CH - 1) / SCAN_CH)   // 196

// ---- scratch (device globals; no allocations allowed) ----
__device__ int   g_degout_i[N_NODES];
__device__ int   g_degin_i[N_NODES];
__device__ float g_invout[N_NODES];
__device__ float g_invin[N_NODES];
__device__ int   g_part[SCAN_NB];
__device__ int   g_off[N_NODES + 1];
__device__ int   g_cursor[N_NODES];
__device__ int   g_esrc[N_EDGES];
__device__ float g_h1[(size_t)N_NODES * U];   // (x * d_out^-1/2) @ W1
__device__ float g_h2[(size_t)N_NODES * C];   // (relu(L1 out) * d_out^-1/2) @ W2

// ---------------------------------------------------------------------------
__global__ void zero_deg_kernel() {
    int i = blockIdx.x * blockDim.x + threadIdx.x;
    if (i < N_NODES) { g_degout_i[i] = 0; g_degin_i[i] = 0; }
}

__global__ void hist_kernel(const int* __restrict__ src, const int* __restrict__ dst) {
    int e = blockIdx.x * blockDim.x + threadIdx.x;
    if (e >= N_EDGES) return;
    atomicAdd(&g_degout_i[src[e]], 1);
    atomicAdd(&g_degin_i[dst[e]], 1);
}

__global__ void invsqrt_kernel() {
    int n = blockIdx.x * blockDim.x + threadIdx.x;
    if (n >= N_NODES) return;
    g_invout[n] = rsqrtf(fmaxf((float)g_degout_i[n], 1.0f));
    g_invin[n]  = rsqrtf(fmaxf((float)g_degin_i[n],  1.0f));
}

// ---------------------------------------------------------------------------
// GEMM1: h1[n,u] = invout[n] * sum_k x[n,k]*W1[k,u]
// 64-node x 32-u tile, 128 threads, 4x4 per thread.
// x tile stored TRANSPOSED (sXT[k][n], stride 68 = 16B aligned) so the inner
// loop is 2x LDS.128 per 16 FFMA instead of 4x LDS.32 + 1x LDS.128.
#define TILE_N 64
#define KT     64
#define XSTR   (TILE_N + 4)    // 68 floats: 16B-aligned rows, bank-shift 4
__global__ void __launch_bounds__(128) gemm1_kernel(const float* __restrict__ x,
                                                    const float* __restrict__ W1) {
    __shared__ float sXT[KT * XSTR];
    __shared__ float sW[KT][U];

    const int t  = threadIdx.x;
    const int ug = t & 7;
    const int ng = t >> 3;
    const int n0 = blockIdx.x * TILE_N;

    float acc[4][4] = {};

    for (int k0 = 0; k0 < F_IN; k0 += KT) {
        for (int i = t; i < KT * U; i += 128)
            ((float*)sW)[i] = W1[k0 * U + i];
        for (int i = t; i < TILE_N * KT; i += 128) {
            int n = i >> 6;            // node within tile
            int k = i & (KT - 1);      // k within tile (consecutive per thread -> coalesced LDG)
            int gn = n0 + n;
            sXT[k * XSTR + n] = (gn < N_NODES) ? x[(size_t)gn * F_IN + k0 + k] : 0.f;
        }
        __syncthreads();
#pragma unroll
        for (int k = 0; k < KT; k++) {
            float4 w  = *(const float4*)&sW[k][ug * 4];
            float4 xv = *(const float4*)&sXT[k * XSTR + ng * 4];
            acc[0][0] += xv.x * w.x; acc[0][1] += xv.x * w.y; acc[0][2] += xv.x * w.z; acc[0][3] += xv.x * w.w;
            acc[1][0] += xv.y * w.x; acc[1][1] += xv.y * w.y; acc[1][2] += xv.y * w.z; acc[1][3] += xv.y * w.w;
            acc[2][0] += xv.z * w.x; acc[2][1] += xv.z * w.y; acc[2][2] += xv.z * w.z; acc[2][3] += xv.z * w.w;
            acc[3][0] += xv.w * w.x; acc[3][1] += xv.w * w.y; acc[3][2] += xv.w * w.z; acc[3][3] += xv.w * w.w;
        }
        __syncthreads();
    }

#pragma unroll
    for (int i = 0; i < 4; i++) {
        int n = n0 + ng * 4 + i;
        if (n < N_NODES) {
            float s = g_invout[n];
            float4 o;
            o.x = acc[i][0] * s; o.y = acc[i][1] * s;
            o.z = acc[i][2] * s; o.w = acc[i][3] * s;
            *(float4*)&g_h1[(size_t)n * U + ug * 4] = o;
        }
    }
}

// ---------------------------------------------------------------------------
__global__ void __launch_bounds__(SCAN_CH) scan_part_kernel() {
    __shared__ int sw[SCAN_CH / 32];
    const int t = threadIdx.x;
    const int i = blockIdx.x * SCAN_CH + t;
    int v = (i < N_NODES) ? g_degin_i[i] : 0;
#pragma unroll
    for (int o = 16; o; o >>= 1) v += __shfl_xor_sync(0xffffffffu, v, o);
    if ((t & 31) == 0) sw[t >> 5] = v;
    __syncthreads();
    if (t < SCAN_CH / 32) {
        int s = sw[t];
#pragma unroll
        for (int o = SCAN_CH / 64; o; o >>= 1) s += __shfl_xor_sync(0xffffffffu, s, o);
        if (t == 0) g_part[blockIdx.x] = s;
    }
}

__global__ void scan_mid_kernel() {
    __shared__ int s[256];
    const int t = threadIdx.x;
    int v = (t < SCAN_NB) ? g_part[t] : 0;
    s[t] = v;
    __syncthreads();
#pragma unroll
    for (int off = 1; off < 256; off <<= 1) {
        int u = (t >= off) ? s[t - off] : 0;
        __syncthreads();
        s[t] += u;
        __syncthreads();
    }
    if (t < SCAN_NB) g_part[t] = s[t] - v;
}

__global__ void __launch_bounds__(SCAN_CH) scan_write_kernel() {
    __shared__ int s[SCAN_CH];
    const int t = threadIdx.x;
    const int i = blockIdx.x * SCAN_CH + t;
    int v = (i < N_NODES) ? g_degin_i[i] : 0;
    s[t] = v;
    __syncthreads();
#pragma unroll
    for (int off = 1; off < SCAN_CH; off <<= 1) {
        int u = (t >= off) ? s[t - off] : 0;
        __syncthreads();
        s[t] += u;
        __syncthreads();
    }
    if (i < N_NODES) {
        int off = g_part[blockIdx.x] + s[t] - v;
        g_off[i] = off;
        g_cursor[i] = off;
    }
    if (i == 0) g_off[N_NODES] = N_EDGES;
}

__global__ void reorder_kernel(const int* __restrict__ src, const int* __restrict__ dst) {
    int e = blockIdx.x * blockDim.x + threadIdx.x;
    if (e >= N_EDGES) return;
    int pos = atomicAdd(&g_cursor[dst[e]], 1);
    g_esrc[pos] = src[e];
}

// ---------------------------------------------------------------------------
// Aggregation layer 1 + relu + GEMM2, fused. One warp per node; lane=feature.
// Edge loop runs in predicated full-width 32-edge batches: indices clamped to
// end-1 (loads always valid & in flight), accumulate predicated on i < cnt.
__global__ void __launch_bounds__(256) agg1_kernel(const float* __restrict__ b1,
                                                   const float* __restrict__ W2) {
    __shared__ float sW2[U * C];
    for (int i = threadIdx.x; i < U * C; i += 256) sW2[i] = W2[i];
    __syncthreads();

    const int n = (blockIdx.x * blockDim.x + threadIdx.x) >> 5;
    const int lane = threadIdx.x & 31;
    if (n >= N_NODES) return;
    const int start = g_off[n], end = g_off[n + 1];

    float acc = 0.f;
    for (int e = start; e < end; e += 32) {
        const int idx = e + lane;
        const int sv = g_esrc[idx < end ? idx : end - 1];
        const int cnt = end - e;
        float a0 = 0.f, a1 = 0.f, a2 = 0.f, a3 = 0.f;
#pragma unroll
        for (int i = 0; i < 32; i += 4) {
            int s0 = __shfl_sync(0xffffffffu, sv, i);
            int s1 = __shfl_sync(0xffffffffu, sv, i + 1);
            int s2 = __shfl_sync(0xffffffffu, sv, i + 2);
            int s3 = __shfl_sync(0xffffffffu, sv, i + 3);
            float v0 = g_h1[(size_t)s0 * U + lane];
            float v1 = g_h1[(size_t)s1 * U + lane];
            float v2 = g_h1[(size_t)s2 * U + lane];
            float v3 = g_h1[(size_t)s3 * U + lane];
            if (i + 0 < cnt) a0 += v0;
            if (i + 1 < cnt) a1 += v1;
            if (i + 2 < cnt) a2 += v2;
            if (i + 3 < cnt) a3 += v3;
        }
        acc += (a0 + a1) + (a2 + a3);
    }

    // relu(norm + bias)
    const float v = fmaxf(acc * g_invin[n] + b1[lane], 0.f);

    // fused gemm2: h2[n,j] = invout[n] * sum_k v[k] * W2[k,j]
    float o0 = 0.f, o1 = 0.f;
#pragma unroll
    for (int k = 0; k < U; k++) {
        float h = __shfl_sync(0xffffffffu, v, k);
        o0 += h * sW2[k * C + lane];
        if (lane < 8) o1 += h * sW2[k * C + 32 + lane];
    }
    const float so = g_invout[n];
    g_h2[(size_t)n * C + lane] = o0 * so;
    if (lane < 8) g_h2[(size_t)n * C + 32 + lane] = o1 * so;
}

// ---------------------------------------------------------------------------
// Aggregation layer 2 (predicated batched gather) + norm + bias + log_softmax.
__global__ void agg2_kernel(float* __restrict__ out, const float* __restrict__ b2) {
    const int n = (blockIdx.x * blockDim.x + threadIdx.x) >> 5;
    const int lane = threadIdx.x & 31;
    if (n >= N_NODES) return;
    const int start = g_off[n], end = g_off[n + 1];

    float acc0 = 0.f, acc1 = 0.f;
    for (int e = start; e < end; e += 32) {
        const int idx = e + lane;
        const int sv = g_esrc[idx < end ? idx : end - 1];
        const int cnt = end - e;
#pragma unroll
        for (int i = 0; i < 32; i++) {
            int s = __shfl_sync(0xffffffffu, sv, i);
            float v0 = g_h2[(size_t)s * C + lane];
            float v1 = (lane < 8) ? g_h2[(size_t)s * C + 32 + lane] : 0.f;
            if (i < cnt) { acc0 += v0; acc1 += v1; }
        }
    }

    const float inv = g_invin[n];
    const float NEG_INF = __int_as_float(0xff800000);
    float v0 = acc0 * inv + b2[lane];
    float v1 = (lane < 8) ? (acc1 * inv + b2[32 + lane]) : NEG_INF;

    float m = fmaxf(v0, v1);
#pragma unroll
    for (int o = 16; o; o >>= 1) m = fmaxf(m, __shfl_xor_sync(0xffffffffu, m, o));
    float se = expf(v0 - m) + ((lane < 8) ? expf(v1 - m) : 0.f);
#pragma unroll
    for (int o = 16; o; o >>= 1) se += __shfl_xor_sync(0xffffffffu, se, o);
    const float ls = logf(se);

    float* row = out + (size_t)n * C;
    row[lane] = v0 - m - ls;
    if (lane < 8) row[32 + lane] = v1 - m - ls;
}

// ---------------------------------------------------------------------------
extern "C" void kernel_launch(void* const* d_in, const int* in_sizes, int n_in,
                              void* d_out, int out_size) {
    const float* x   = (const float*)d_in[0];
    const float* W1  = (const float*)d_in[1];
    const float* b1  = (const float*)d_in[2];
    const float* W2  = (const float*)d_in[3];
    const float* b2  = (const float*)d_in[4];
    const int*   src = (const int*)d_in[5];
    const int*   dst = (const int*)d_in[6];
    float* out = (float*)d_out;

    zero_deg_kernel<<<(N_NODES + 255) / 256, 256>>>();
    hist_kernel<<<(N_EDGES + 255) / 256, 256>>>(src, dst);
    invsqrt_kernel<<<(N_NODES + 255) / 256, 256>>>();
    gemm1_kernel<<<(N_NODES + TILE_N - 1) / TILE_N, 128>>>(x, W1);   // slot #4 -> profiled
    scan_part_kernel<<<SCAN_NB, SCAN_CH>>>();
    scan_mid_kernel<<<1, 256>>>();
    scan_write_kernel<<<SCAN_NB, SCAN_CH>>>();
    reorder_kernel<<<(N_EDGES + 255) / 256, 256>>>(src, dst);
    agg1_kernel<<<(N_NODES * 32 + 255) / 256, 256>>>(b1, W2);
    agg2_kernel<<<(N_NODES * 32 + 255) / 256, 256>>>(out, b2);
}